// round 10
// baseline (speedup 1.0000x reference)
#include <cuda_runtime.h>
#include <cuda_fp16.h>
#include <math.h>
#include <stdint.h>

#define BB   32
#define SS   4096
#define HID  512
#define MEMD 512
#define ATT  512

// ------------------------------- scratch -----------------------------------
__device__ float g_scores[BB * SS];
__device__ float g_h[BB * ATT];
// W_m permuted into per-thread fp16 fragment order for m16n8k16, BN=128 tiles.
// uint (half2) layout: [n0t(4)][stage(16)][i8(8)][chunk(64)][e(4)]
//   i8 = kk*4 + kb*2 + jq ; j = jq*4 + e ; chunk = warpN*32 + lane
//   half2 = { W[k][n], W[k+1][n] },  k = s*32 + kk*16 + kb*8 + 2*tg
//   n = n0t*128 + warpN*64 + j*8 + g
__device__ unsigned int g_Wp16[4 * 16 * 8 * 64 * 4];

// ------------------------------- helpers -----------------------------------
__device__ __forceinline__ uint32_t smem_u32(const void* p) {
    return (uint32_t)__cvta_generic_to_shared(p);
}
__device__ __forceinline__ void cp16(uint32_t dst, const void* src) {
    asm volatile("cp.async.cg.shared.global [%0], [%1], 16;\n" :: "r"(dst), "l"(src));
}
__device__ __forceinline__ void cp_commit() { asm volatile("cp.async.commit_group;\n" ::: "memory"); }
template <int N>
__device__ __forceinline__ void cp_wait() {
    asm volatile("cp.async.wait_group %0;\n" :: "n"(N) : "memory");
}
// pack (x=k_even, y=k_odd) -> f16x2 reg (lo = x)
__device__ __forceinline__ uint32_t pack_f16x2(float x, float y) {
    uint32_t d;
    asm("cvt.rn.f16x2.f32 %0, %1, %2;" : "=r"(d) : "f"(y), "f"(x));
    return d;
}
__device__ __forceinline__ void mma_f16(float* d, uint32_t a0, uint32_t a1,
                                        uint32_t a2, uint32_t a3,
                                        uint32_t b0, uint32_t b1) {
    asm volatile(
        "mma.sync.aligned.m16n8k16.row.col.f32.f16.f16.f32 "
        "{%0,%1,%2,%3}, {%4,%5,%6,%7}, {%8,%9}, {%0,%1,%2,%3};"
        : "+f"(d[0]), "+f"(d[1]), "+f"(d[2]), "+f"(d[3])
        : "r"(a0), "r"(a1), "r"(a2), "r"(a3), "r"(b0), "r"(b1));
}
__device__ __forceinline__ void ldmatrix_x4(uint32_t& a0, uint32_t& a1,
                                            uint32_t& a2, uint32_t& a3,
                                            uint32_t addr) {
    asm volatile("ldmatrix.sync.aligned.m8n8.x4.shared.b16 {%0,%1,%2,%3}, [%4];"
                 : "=r"(a0), "=r"(a1), "=r"(a2), "=r"(a3) : "r"(addr));
}
__device__ __forceinline__ void sts128(uint32_t addr, uint32_t x, uint32_t y,
                                       uint32_t z, uint32_t w) {
    asm volatile("st.shared.v4.b32 [%0], {%1,%2,%3,%4};"
                 :: "r"(addr), "r"(x), "r"(y), "r"(z), "r"(w) : "memory");
}
__device__ __forceinline__ float tanh_fast(float x) {
    float y; asm("tanh.approx.f32 %0, %1;" : "=f"(y) : "f"(x)); return y;
}

// ---------------------------------------------------------------------------
// zero: scores scratch + context output region
// ---------------------------------------------------------------------------
__global__ void zero_kernel(float* __restrict__ out_ctx) {
    int i = blockIdx.x * blockDim.x + threadIdx.x;
    if (i < BB * SS) g_scores[i] = 0.0f;
    if (i < BB * MEMD) out_ctx[i] = 0.0f;
}

// ---------------------------------------------------------------------------
// Build g_Wp16 (fp16 permuted fragment layout, BN=128). One thread per half2.
// ---------------------------------------------------------------------------
__global__ void permute_wm16(const float* __restrict__ Wm) {
    int o = blockIdx.x * blockDim.x + threadIdx.x;
    if (o >= 4 * 16 * 8 * 64 * 4) return;
    int e     = o & 3;
    int chunk = (o >> 2) & 63;
    int i8    = (o >> 8) & 7;
    int s     = (o >> 11) & 15;
    int n0t   = o >> 15;
    int kk = i8 >> 2, kb = (i8 >> 1) & 1, jq = i8 & 1;
    int j = jq * 4 + e;
    int lane = chunk & 31, warpN = chunk >> 5;
    int g = lane >> 2, tg = lane & 3;
    int k = s * 32 + kk * 16 + kb * 8 + 2 * tg;
    int n = n0t * 128 + warpN * 64 + j * 8 + g;
    __half2 h = __floats2half2_rn(Wm[k * ATT + n], Wm[(k + 1) * ATT + n]);
    g_Wp16[o] = *reinterpret_cast<unsigned int*>(&h);
}

// ---------------------------------------------------------------------------
// h[b][a] = hidden[b] . W_h[:,a]   grid=B, block=512
// ---------------------------------------------------------------------------
__global__ void h_kernel(const float* __restrict__ hidden,
                         const float* __restrict__ W_h) {
    __shared__ float sh[HID];
    int b = blockIdx.x;
    int a = threadIdx.x;
    sh[a] = hidden[b * HID + a];
    __syncthreads();
    float acc = 0.0f;
#pragma unroll 8
    for (int d = 0; d < HID; d++) acc += sh[d] * W_h[d * ATT + a];
    g_h[b * ATT + a] = acc;
}

// ---------------------------------------------------------------------------
// Score GEMM (fp16 m16n8k16, fp32 accumulate) + tanh/v epilogue.
// CTA 128x128, 8 warps (4M x 2N), warp tile 32x64, 256 threads, 2 CTAs/SM.
// A: LDG fp32 -> cvt fp16 -> STS (row stride 80B, conflict-free), fragments
//    via ldmatrix.x4. 2-stage A buffer + 1-stage register staging.
// B: cp.async of pre-permuted fp16, LDS.128 fragments, 3-stage buffer.
// grid = (4 n-tiles, 1024 m-tiles).
// ---------------------------------------------------------------------------
#define BM 128
#define BN 128
#define BK 32
#define A16_STRIDE_B 80               // bytes per A row (40 halves)
#define A16_TILE_B   (BM * A16_STRIDE_B)   // 10240 B / stage
#define B_TILE_U (8 * 64 * 4)         // 2048 uints / stage (8KB)
#define NSTAGE (MEMD / BK)            // 16
#define A_BYTES (2 * A16_TILE_B)              // 20480
#define B_BYTES (3 * B_TILE_U * 4)            // 24576
#define AUX_FLOATS (3 * 512)
#define SMEM_DYN (A_BYTES + B_BYTES + AUX_FLOATS * 4)

__global__ void __launch_bounds__(256, 2) score_mma(
    const float* __restrict__ Amem,
    const float* __restrict__ coverage,
    const float* __restrict__ Wc,
    const float* __restrict__ vvec) {

    extern __shared__ float dsm[];
    uint32_t smem = smem_u32(dsm);
    const uint32_t A16 = smem;                        // 2 x 10240 B
    unsigned int* Bs_all = (unsigned int*)((char*)dsm + A_BYTES);
    float* sh_h  = (float*)((char*)dsm + A_BYTES + B_BYTES);
    float* sh_wc = sh_h + 512;
    float* sh_v  = sh_wc + 512;

    const int tid   = threadIdx.x;
    const int lane  = tid & 31;
    const int wid   = tid >> 5;     // 0..7
    const int warpN = wid & 1;      // 0..1
    const int warpM = wid >> 1;     // 0..3
    const int g     = lane >> 2;    // 0..7
    const int tg    = lane & 3;     // 0..3
    const int chunkB = warpN * 32 + lane;

    const int  n0t  = blockIdx.x;
    const int  n0   = n0t * BN;
    const long row0 = (long)blockIdx.y * BM;
    const int  b    = (int)(row0 >> 12);

    for (int i = tid; i < 512; i += 256) {
        sh_h[i]  = g_h[b * 512 + i];
        sh_wc[i] = Wc[i];
        sh_v[i]  = vvec[i];
    }

    float acc[2][8][4];
#pragma unroll
    for (int i = 0; i < 2; i++)
#pragma unroll
        for (int j = 0; j < 8; j++)
#pragma unroll
            for (int c = 0; c < 4; c++) acc[i][j][c] = 0.0f;

    // ---- A loader mapping: thread -> (row, 16-half column chunk) ----
    const int lrow = ((tid >> 5) << 4) + (tid & 15);    // 0..127
    const int lch  = (tid >> 4) & 1;                    // 0..1
    const float* gA = Amem + (row0 + lrow) * 512 + lch * 16;
    const uint32_t stsBase = A16 + lrow * A16_STRIDE_B + lch * 32;

    // ldmatrix per-thread base: lane -> (row within 16, k-half)
    const uint32_t lmBase = A16 + (lane & 15) * A16_STRIDE_B + (lane >> 4) * 16;

    float4 st0, st1, st2, st3;   // staging registers (one stage)

    auto ldgA = [&](int s) {
        const float4* p = (const float4*)(gA + s * BK);
        st0 = p[0]; st1 = p[1]; st2 = p[2]; st3 = p[3];
    };
    auto stsA = [&](int s) {
        uint32_t a = stsBase + (s & 1) * A16_TILE_B;
        sts128(a,
               pack_f16x2(st0.x, st0.y), pack_f16x2(st0.z, st0.w),
               pack_f16x2(st1.x, st1.y), pack_f16x2(st1.z, st1.w));
        sts128(a + 16,
               pack_f16x2(st2.x, st2.y), pack_f16x2(st2.z, st2.w),
               pack_f16x2(st3.x, st3.y), pack_f16x2(st3.z, st3.w));
    };
    const unsigned int* BsrcBase = g_Wp16 + (long)n0t * 16 * B_TILE_U;
    auto cpB = [&](int s) {
        uint32_t Bbu = smem_u32(Bs_all + (s % 3) * B_TILE_U);
        const unsigned int* Bsrc = BsrcBase + (long)s * B_TILE_U;
#pragma unroll
        for (int j = 0; j < 2; j++) {
            int u4 = tid + 256 * j;
            cp16(Bbu + u4 * 16, Bsrc + u4 * 4);
        }
        cp_commit();
    };

    // ---- preamble ----
    ldgA(0); stsA(0);
    ldgA(1);
    cpB(0); cpB(1);
    cp_wait<1>();
    __syncthreads();

    for (int s = 0; s < NSTAGE; s++) {
        // ---- compute stage s ----
        const uint4* B4 = (const uint4*)(Bs_all + (s % 3) * B_TILE_U);
        const uint32_t abuf = lmBase + (s & 1) * A16_TILE_B;

#pragma unroll
        for (int kk = 0; kk < 2; kk++) {
            uint4 q0 = B4[(kk * 4 + 0) * 64 + chunkB];
            uint4 q1 = B4[(kk * 4 + 1) * 64 + chunkB];
            uint4 q2 = B4[(kk * 4 + 2) * 64 + chunkB];
            uint4 q3 = B4[(kk * 4 + 3) * 64 + chunkB];
            uint32_t b0[8] = {q0.x, q0.y, q0.z, q0.w, q1.x, q1.y, q1.z, q1.w};
            uint32_t b1[8] = {q2.x, q2.y, q2.z, q2.w, q3.x, q3.y, q3.z, q3.w};

#pragma unroll
            for (int i = 0; i < 2; i++) {
                uint32_t a0, a1, a2, a3;
                ldmatrix_x4(a0, a1, a2, a3,
                            abuf + (warpM * 32 + i * 16) * A16_STRIDE_B + kk * 32);
#pragma unroll
                for (int j = 0; j < 8; j++)
                    mma_f16(acc[i][j], a0, a1, a2, a3, b0[j], b1[j]);
            }
        }

        // ---- pipeline maintenance ----
        if (s + 1 < NSTAGE) stsA(s + 1);
        if (s + 2 < NSTAGE) { ldgA(s + 2); cpB(s + 2); }
        if (s + 1 < NSTAGE) {
            if (s + 2 < NSTAGE) cp_wait<1>(); else cp_wait<0>();
            __syncthreads();
        }
    }

    // ---- epilogue: tanh + v-dot partial over this CTA's 128 n-cols ----
#pragma unroll
    for (int i = 0; i < 2; i++) {
        const int r_lo = warpM * 32 + i * 16 + g;
        const int r_hi = r_lo + 8;
        const float cov_lo = coverage[row0 + r_lo];
        const float cov_hi = coverage[row0 + r_hi];
        float p_lo = 0.0f, p_hi = 0.0f;
#pragma unroll
        for (int j = 0; j < 8; j++) {
            const int nb = n0 + warpN * 64 + j * 8 + tg * 2;  // absolute col
            const float h0 = sh_h[nb + 0], h1 = sh_h[nb + 1];
            const float w0 = sh_wc[nb + 0], w1 = sh_wc[nb + 1];
            const float v0 = sh_v[nb + 0], v1 = sh_v[nb + 1];
            p_lo += tanh_fast(acc[i][j][0] + h0 + cov_lo * w0) * v0;
            p_lo += tanh_fast(acc[i][j][1] + h1 + cov_lo * w1) * v1;
            p_hi += tanh_fast(acc[i][j][2] + h0 + cov_hi * w0) * v0;
            p_hi += tanh_fast(acc[i][j][3] + h1 + cov_hi * w1) * v1;
        }
        p_lo += __shfl_xor_sync(0xffffffffu, p_lo, 1);
        p_lo += __shfl_xor_sync(0xffffffffu, p_lo, 2);
        p_hi += __shfl_xor_sync(0xffffffffu, p_hi, 1);
        p_hi += __shfl_xor_sync(0xffffffffu, p_hi, 2);
        if (tg == 0) {
            atomicAdd(&g_scores[row0 + r_lo], p_lo);
            atomicAdd(&g_scores[row0 + r_hi], p_hi);
        }
    }
}

// ---------------------------------------------------------------------------
// Softmax over S per batch (with pad mask). grid=B, block=1024.
// ---------------------------------------------------------------------------
__global__ void softmax_kernel(const unsigned char* __restrict__ pad,
                               float* __restrict__ attn) {
    __shared__ float red[1024];
    const int b = blockIdx.x;
    const int tid = threadIdx.x;

    float mx = -INFINITY;
    for (int s = tid; s < SS; s += 1024) {
        float sc = pad[b * SS + s] ? -INFINITY : g_scores[b * SS + s];
        mx = fmaxf(mx, sc);
    }
    red[tid] = mx;
    __syncthreads();
    for (int off = 512; off > 0; off >>= 1) {
        if (tid < off) red[tid] = fmaxf(red[tid], red[tid + off]);
        __syncthreads();
    }
    mx = red[0];
    __syncthreads();

    float sum = 0.0f;
    for (int s = tid; s < SS; s += 1024) {
        float sc = pad[b * SS + s] ? -INFINITY : g_scores[b * SS + s];
        float e = expf(sc - mx);
        attn[b * SS + s] = e;
        sum += e;
    }
    red[tid] = sum;
    __syncthreads();
    for (int off = 512; off > 0; off >>= 1) {
        if (tid < off) red[tid] += red[tid + off];
        __syncthreads();
    }
    float inv = 1.0f / red[0];
    for (int s = tid; s < SS; s += 1024) attn[b * SS + s] *= inv;
}

// ---------------------------------------------------------------------------
// context[b][d] = sum_s attn[b][s] * memory[b][s][d]. grid=(B,32), block=512.
// ---------------------------------------------------------------------------
__global__ void context_kernel(const float* __restrict__ memory,
                               const float* __restrict__ attn,
                               float* __restrict__ ctx) {
    __shared__ float w[128];
    const int b = blockIdx.x;
    const int s0 = blockIdx.y * 128;
    const int d = threadIdx.x;

    if (d < 128) w[d] = attn[b * SS + s0 + d];
    __syncthreads();

    float acc = 0.0f;
    const float* mbase = memory + ((long)b * SS + s0) * MEMD + d;
#pragma unroll 4
    for (int s = 0; s < 128; s++) acc += w[s] * mbase[(long)s * MEMD];
    atomicAdd(&ctx[b * MEMD + d], acc);
}

// ---------------------------------------------------------------------------
// Launch.  Inputs (metadata order):
//   0 hidden | 1 memory | 2 mem_pad | 3 coverage | 4 W_h | 5 W_m | 6 W_c | 7 v
// Output: [context (B*MEM) | attn (B*S)] f32
// ---------------------------------------------------------------------------
extern "C" void kernel_launch(void* const* d_in, const int* in_sizes, int n_in,
                              void* d_out, int out_size) {
    const float* hidden   = (const float*)d_in[0];
    const float* memory   = (const float*)d_in[1];
    const unsigned char* mem_pad = (const unsigned char*)d_in[2];
    const float* coverage = (const float*)d_in[3];
    const float* W_h      = (const float*)d_in[4];
    const float* W_m      = (const float*)d_in[5];
    const float* W_c      = (const float*)d_in[6];
    const float* v        = (const float*)d_in[7];

    float* out = (float*)d_out;
    float* out_ctx  = out;
    float* out_attn = out + BB * MEMD;

    cudaFuncSetAttribute(score_mma, cudaFuncAttributeMaxDynamicSharedMemorySize,
                         SMEM_DYN);

    zero_kernel<<<(BB * SS + 255) / 256, 256>>>(out_ctx);
    permute_wm16<<<(4 * 16 * 8 * 64 * 4 + 255) / 256, 256>>>(W_m);
    h_kernel<<<BB, 512>>>(hidden, W_h);
    {
        dim3 grid(ATT / BN, BB * SS / BM);
        score_mma<<<grid, 256, SMEM_DYN>>>(memory, coverage, W_c, v);
    }
    softmax_kernel<<<BB, 1024>>>(mem_pad, out_attn);
    {
        dim3 grid(BB, SS / 128);
        context_kernel<<<grid, 512>>>(memory, out_attn, out_ctx);
    }
}

// round 11
// speedup vs baseline: 1.3984x; 1.3984x over previous
#include <cuda_runtime.h>
#include <cuda_fp16.h>
#include <math.h>
#include <stdint.h>

#define BB   32
#define SS   4096
#define HID  512
#define MEMD 512
#define ATT  512

// ------------------------------- scratch -----------------------------------
__device__ float g_scores[BB * SS];
__device__ float g_h[BB * ATT];
// W_m permuted into per-thread fp16 fragment order for m16n8k16, BN=128 tiles.
// uint (half2) layout: [n0t(4)][stage(16)][i8(8)][chunk(64)][e(4)]
//   i8 = kk*4 + kb*2 + jq ; j = jq*4 + e ; chunk = warpN*32 + lane
//   half2 = { W[k][n], W[k+1][n] },  k = s*32 + kk*16 + kb*8 + 2*tg
//   n = n0t*128 + warpN*64 + j*8 + g
__device__ unsigned int g_Wp16[4 * 16 * 8 * 64 * 4];

// ------------------------------- helpers -----------------------------------
__device__ __forceinline__ uint32_t smem_u32(const void* p) {
    return (uint32_t)__cvta_generic_to_shared(p);
}
__device__ __forceinline__ void cp16(uint32_t dst, const void* src) {
    asm volatile("cp.async.cg.shared.global [%0], [%1], 16;\n" :: "r"(dst), "l"(src));
}
__device__ __forceinline__ void cp_commit() { asm volatile("cp.async.commit_group;\n" ::: "memory"); }
template <int N>
__device__ __forceinline__ void cp_wait() {
    asm volatile("cp.async.wait_group %0;\n" :: "n"(N) : "memory");
}
// pack float2 {x=k_even, y=k_odd} -> f16x2 reg (lo = x)
__device__ __forceinline__ uint32_t pack_f16x2(float2 p) {
    uint32_t d;
    asm("cvt.rn.f16x2.f32 %0, %1, %2;" : "=r"(d) : "f"(p.y), "f"(p.x));
    return d;
}
__device__ __forceinline__ void mma_f16(float* d, uint32_t a0, uint32_t a1,
                                        uint32_t a2, uint32_t a3,
                                        uint32_t b0, uint32_t b1) {
    asm volatile(
        "mma.sync.aligned.m16n8k16.row.col.f32.f16.f16.f32 "
        "{%0,%1,%2,%3}, {%4,%5,%6,%7}, {%8,%9}, {%0,%1,%2,%3};"
        : "+f"(d[0]), "+f"(d[1]), "+f"(d[2]), "+f"(d[3])
        : "r"(a0), "r"(a1), "r"(a2), "r"(a3), "r"(b0), "r"(b1));
}
__device__ __forceinline__ float tanh_fast(float x) {
    float y; asm("tanh.approx.f32 %0, %1;" : "=f"(y) : "f"(x)); return y;
}

// ---------------------------------------------------------------------------
// zero: scores scratch + context output region
// ---------------------------------------------------------------------------
__global__ void zero_kernel(float* __restrict__ out_ctx) {
    int i = blockIdx.x * blockDim.x + threadIdx.x;
    if (i < BB * SS) g_scores[i] = 0.0f;
    if (i < BB * MEMD) out_ctx[i] = 0.0f;
}

// ---------------------------------------------------------------------------
// Build g_Wp16 (fp16 permuted fragment layout, BN=128). One thread per half2.
// ---------------------------------------------------------------------------
__global__ void permute_wm16(const float* __restrict__ Wm) {
    int o = blockIdx.x * blockDim.x + threadIdx.x;
    if (o >= 4 * 16 * 8 * 64 * 4) return;
    int e     = o & 3;
    int chunk = (o >> 2) & 63;
    int i8    = (o >> 8) & 7;
    int s     = (o >> 11) & 15;
    int n0t   = o >> 15;
    int kk = i8 >> 2, kb = (i8 >> 1) & 1, jq = i8 & 1;
    int j = jq * 4 + e;
    int lane = chunk & 31, warpN = chunk >> 5;
    int g = lane >> 2, tg = lane & 3;
    int k = s * 32 + kk * 16 + kb * 8 + 2 * tg;
    int n = n0t * 128 + warpN * 64 + j * 8 + g;
    __half2 h = __floats2half2_rn(Wm[k * ATT + n], Wm[(k + 1) * ATT + n]);
    g_Wp16[o] = *reinterpret_cast<unsigned int*>(&h);
}

// ---------------------------------------------------------------------------
// h[b][a] = hidden[b] . W_h[:,a]   grid=B, block=512
// ---------------------------------------------------------------------------
__global__ void h_kernel(const float* __restrict__ hidden,
                         const float* __restrict__ W_h) {
    __shared__ float sh[HID];
    int b = blockIdx.x;
    int a = threadIdx.x;
    sh[a] = hidden[b * HID + a];
    __syncthreads();
    float acc = 0.0f;
#pragma unroll 8
    for (int d = 0; d < HID; d++) acc += sh[d] * W_h[d * ATT + a];
    g_h[b * ATT + a] = acc;
}

// ---------------------------------------------------------------------------
// Score GEMM (fp16 m16n8k16, fp32 accumulate) + tanh/v epilogue.
// CTA tile 128(M) x 128(N), 8 warps (4M x 2N), warp tile 32x64, 256 threads.
// 2 CTAs/SM. A fp32 in smem (AST=40, conflict-free); B pre-permuted fp16.
// 3-stage cp.async pipeline; all B fragment loads front-loaded per stage.
// grid = (4 n-tiles, 1024 m-tiles).
// ---------------------------------------------------------------------------
#define BM 128
#define BN 128
#define BK 32
#define AST 40                        // conflict-free for fragment LDS.64
#define A_TILE (BM * AST)             // 5120 floats / stage (20KB)
#define B_TILE_U (8 * 64 * 4)         // 2048 uints / stage (8KB)
#define NSTAGE (MEMD / BK)            // 16
#define AUX_OFF (3 * A_TILE + 3 * B_TILE_U)
#define SMEM_DYN ((AUX_OFF + 3 * 512) * 4)

__global__ void __launch_bounds__(256, 2) score_mma(
    const float* __restrict__ Amem,
    const float* __restrict__ coverage,
    const float* __restrict__ Wc,
    const float* __restrict__ vvec) {

    extern __shared__ float dsm[];
    float* As_all = dsm;                                      // 3 * A_TILE fp32
    unsigned int* Bs_all = (unsigned int*)(dsm + 3 * A_TILE); // 3 * B_TILE_U
    float* sh_h   = dsm + AUX_OFF;                            // 512 (absolute)
    float* sh_wc  = sh_h + 512;
    float* sh_v   = sh_wc + 512;

    const int tid   = threadIdx.x;
    const int lane  = tid & 31;
    const int wid   = tid >> 5;     // 0..7
    const int warpN = wid & 1;      // 0..1
    const int warpM = wid >> 1;     // 0..3
    const int g     = lane >> 2;    // 0..7
    const int tg    = lane & 3;     // 0..3
    const int chunkB = warpN * 32 + lane;

    const int  n0t  = blockIdx.x;
    const int  n0   = n0t * BN;
    const long row0 = (long)blockIdx.y * BM;
    const int  b    = (int)(row0 >> 12);

    for (int i = tid; i < 512; i += 256) {
        sh_h[i]  = g_h[b * 512 + i];
        sh_wc[i] = Wc[i];
        sh_v[i]  = vvec[i];
    }

    float acc[2][8][4];
#pragma unroll
    for (int i = 0; i < 2; i++)
#pragma unroll
        for (int j = 0; j < 8; j++)
#pragma unroll
            for (int c = 0; c < 4; c++) acc[i][j][c] = 0.0f;

    const unsigned int* BsrcBase = g_Wp16 + (long)n0t * 16 * B_TILE_U;

    auto load_stage = [&](int s) {
        const int buf = s % 3;
        uint32_t Abu = smem_u32(As_all + buf * A_TILE);
        uint32_t Bbu = smem_u32(Bs_all + buf * B_TILE_U);
        const int k0 = s * BK;
        // A: 128 rows x 8 float4 = 1024 cp16 over 256 threads -> 4 each
#pragma unroll
        for (int j = 0; j < 4; j++) {
            int c = tid + 256 * j;
            int r = c >> 3, c4 = c & 7;
            cp16(Abu + (r * AST + c4 * 4) * 4, Amem + (row0 + r) * 512 + k0 + c4 * 4);
        }
        // B: 512 uint4 -> 2 each (coalesced)
        const unsigned int* Bsrc = BsrcBase + (long)s * B_TILE_U;
#pragma unroll
        for (int j = 0; j < 2; j++) {
            int u4 = tid + 256 * j;
            cp16(Bbu + u4 * 16, Bsrc + u4 * 4);
        }
        cp_commit();
    };

    load_stage(0);
    load_stage(1);

    for (int s = 0; s < NSTAGE; s++) {
        if (s < NSTAGE - 1) cp_wait<1>(); else cp_wait<0>();
        __syncthreads();
        if (s + 2 < NSTAGE) load_stage(s + 2);

        const int buf = s % 3;
        const float* Ab = As_all + buf * A_TILE;
        const uint4* B4 = (const uint4*)(Bs_all + buf * B_TILE_U);

        // ---- front-load ALL B fragments for this stage (8 x LDS.128) ----
        uint4 q[8];
#pragma unroll
        for (int t = 0; t < 8; t++) q[t] = B4[t * 64 + chunkB];

#pragma unroll
        for (int kk = 0; kk < 2; kk++) {
            uint32_t b0[8] = {q[kk * 4 + 0].x, q[kk * 4 + 0].y, q[kk * 4 + 0].z, q[kk * 4 + 0].w,
                              q[kk * 4 + 1].x, q[kk * 4 + 1].y, q[kk * 4 + 1].z, q[kk * 4 + 1].w};
            uint32_t b1[8] = {q[kk * 4 + 2].x, q[kk * 4 + 2].y, q[kk * 4 + 2].z, q[kk * 4 + 2].w,
                              q[kk * 4 + 3].x, q[kk * 4 + 3].y, q[kk * 4 + 3].z, q[kk * 4 + 3].w};

            // ---- A fragments for both i sub-tiles (8 x LDS.64), then MMAs ----
            const int kbase = kk * 16 + 2 * tg;
            uint32_t af[2][4];
#pragma unroll
            for (int i = 0; i < 2; i++) {
                const int r = warpM * 32 + i * 16 + g;
                float2 p0 = *(const float2*)(Ab + r * AST + kbase);
                float2 p1 = *(const float2*)(Ab + (r + 8) * AST + kbase);
                float2 p2 = *(const float2*)(Ab + r * AST + kbase + 8);
                float2 p3 = *(const float2*)(Ab + (r + 8) * AST + kbase + 8);
                af[i][0] = pack_f16x2(p0);
                af[i][1] = pack_f16x2(p1);
                af[i][2] = pack_f16x2(p2);
                af[i][3] = pack_f16x2(p3);
            }
#pragma unroll
            for (int i = 0; i < 2; i++)
#pragma unroll
                for (int j = 0; j < 8; j++)
                    mma_f16(acc[i][j], af[i][0], af[i][1], af[i][2], af[i][3],
                            b0[j], b1[j]);
        }
    }

    // ---- epilogue: tanh + v-dot partial over this CTA's 128 n-cols ----
#pragma unroll
    for (int i = 0; i < 2; i++) {
        const int r_lo = warpM * 32 + i * 16 + g;
        const int r_hi = r_lo + 8;
        const float cov_lo = coverage[row0 + r_lo];
        const float cov_hi = coverage[row0 + r_hi];
        float p_lo = 0.0f, p_hi = 0.0f;
#pragma unroll
        for (int j = 0; j < 8; j++) {
            const int nb = n0 + warpN * 64 + j * 8 + tg * 2;  // absolute col
            const float h0 = sh_h[nb + 0], h1 = sh_h[nb + 1];
            const float w0 = sh_wc[nb + 0], w1 = sh_wc[nb + 1];
            const float v0 = sh_v[nb + 0], v1 = sh_v[nb + 1];
            p_lo += tanh_fast(acc[i][j][0] + h0 + cov_lo * w0) * v0;
            p_lo += tanh_fast(acc[i][j][1] + h1 + cov_lo * w1) * v1;
            p_hi += tanh_fast(acc[i][j][2] + h0 + cov_hi * w0) * v0;
            p_hi += tanh_fast(acc[i][j][3] + h1 + cov_hi * w1) * v1;
        }
        p_lo += __shfl_xor_sync(0xffffffffu, p_lo, 1);
        p_lo += __shfl_xor_sync(0xffffffffu, p_lo, 2);
        p_hi += __shfl_xor_sync(0xffffffffu, p_hi, 1);
        p_hi += __shfl_xor_sync(0xffffffffu, p_hi, 2);
        if (tg == 0) {
            atomicAdd(&g_scores[row0 + r_lo], p_lo);
            atomicAdd(&g_scores[row0 + r_hi], p_hi);
        }
    }
}

// ---------------------------------------------------------------------------
// Softmax over S per batch (with pad mask). grid=B, block=1024.
// ---------------------------------------------------------------------------
__global__ void softmax_kernel(const unsigned char* __restrict__ pad,
                               float* __restrict__ attn) {
    __shared__ float red[1024];
    const int b = blockIdx.x;
    const int tid = threadIdx.x;

    float mx = -INFINITY;
    for (int s = tid; s < SS; s += 1024) {
        float sc = pad[b * SS + s] ? -INFINITY : g_scores[b * SS + s];
        mx = fmaxf(mx, sc);
    }
    red[tid] = mx;
    __syncthreads();
    for (int off = 512; off > 0; off >>= 1) {
        if (tid < off) red[tid] = fmaxf(red[tid], red[tid + off]);
        __syncthreads();
    }
    mx = red[0];
    __syncthreads();

    float sum = 0.0f;
    for (int s = tid; s < SS; s += 1024) {
        float sc = pad[b * SS + s] ? -INFINITY : g_scores[b * SS + s];
        float e = expf(sc - mx);
        attn[b * SS + s] = e;
        sum += e;
    }
    red[tid] = sum;
    __syncthreads();
    for (int off = 512; off > 0; off >>= 1) {
        if (tid < off) red[tid] += red[tid + off];
        __syncthreads();
    }
    float inv = 1.0f / red[0];
    for (int s = tid; s < SS; s += 1024) attn[b * SS + s] *= inv;
}

// ---------------------------------------------------------------------------
// context[b][d] = sum_s attn[b][s] * memory[b][s][d]. grid=(B,32), block=512.
// ---------------------------------------------------------------------------
__global__ void context_kernel(const float* __restrict__ memory,
                               const float* __restrict__ attn,
                               float* __restrict__ ctx) {
    __shared__ float w[128];
    const int b = blockIdx.x;
    const int s0 = blockIdx.y * 128;
    const int d = threadIdx.x;

    if (d < 128) w[d] = attn[b * SS + s0 + d];
    __syncthreads();

    float acc = 0.0f;
    const float* mbase = memory + ((long)b * SS + s0) * MEMD + d;
#pragma unroll 4
    for (int s = 0; s < 128; s++) acc += w[s] * mbase[(long)s * MEMD];
    atomicAdd(&ctx[b * MEMD + d], acc);
}

// ---------------------------------------------------------------------------
// Launch.  Inputs (metadata order):
//   0 hidden | 1 memory | 2 mem_pad | 3 coverage | 4 W_h | 5 W_m | 6 W_c | 7 v
// Output: [context (B*MEM) | attn (B*S)] f32
// ---------------------------------------------------------------------------
extern "C" void kernel_launch(void* const* d_in, const int* in_sizes, int n_in,
                              void* d_out, int out_size) {
    const float* hidden   = (const float*)d_in[0];
    const float* memory   = (const float*)d_in[1];
    const unsigned char* mem_pad = (const unsigned char*)d_in[2];
    const float* coverage = (const float*)d_in[3];
    const float* W_h      = (const float*)d_in[4];
    const float* W_m      = (const float*)d_in[5];
    const float* W_c      = (const float*)d_in[6];
    const float* v        = (const float*)d_in[7];

    float* out = (float*)d_out;
    float* out_ctx  = out;
    float* out_attn = out + BB * MEMD;

    cudaFuncSetAttribute(score_mma, cudaFuncAttributeMaxDynamicSharedMemorySize,
                         SMEM_DYN);

    zero_kernel<<<(BB * SS + 255) / 256, 256>>>(out_ctx);
    permute_wm16<<<(4 * 16 * 8 * 64 * 4 + 255) / 256, 256>>>(W_m);
    h_kernel<<<BB, 512>>>(hidden, W_h);
    {
        dim3 grid(ATT / BN, BB * SS / BM);
        score_mma<<<grid, 256, SMEM_DYN>>>(memory, coverage, W_c, v);
    }
    softmax_kernel<<<BB, 1024>>>(mem_pad, out_attn);
    {
        dim3 grid(BB, SS / 128);
        context_kernel<<<grid, 512>>>(memory, out_attn, out_ctx);
    }
}